// round 5
// baseline (speedup 1.0000x reference)
#include <cuda_runtime.h>
#include <cstdint>
#include <math_constants.h>

#define NB 32
#define NL 512
#define ND 512
#define NH 8
#define NDH 64
#define MTOT (NB*NL)

// ---------------- scratch (static device memory; no allocs allowed) ----------
__device__ float g_Q[(size_t)MTOT * ND];
__device__ float g_K[(size_t)MTOT * ND];
__device__ float g_V[(size_t)MTOT * ND];
__device__ float g_qm[MTOT];
__device__ float g_km[MTOT];
__device__ float g_linv[NB * NH * NL];

// ---------------- helpers ----------------------------------------------------
__device__ __forceinline__ uint32_t tf32u(float x) {
    uint32_t u;
    asm("cvt.rna.tf32.f32 %0, %1;" : "=r"(u) : "f"(x));
    return u;
}
__device__ __forceinline__ float tf32r(float x) {
    return __uint_as_float(tf32u(x));
}
__device__ __forceinline__ float ex2(float x) {
    float y;
    asm("ex2.approx.ftz.f32 %0, %1;" : "=f"(y) : "f"(x));
    return y;
}
// D = A(16x8 row) * B(8x8 col) + D, tf32 inputs, f32 accum
__device__ __forceinline__ void mma8(float c[4], const uint32_t a[4], uint32_t b0, uint32_t b1) {
    asm volatile(
        "mma.sync.aligned.m16n8k8.row.col.f32.tf32.tf32.f32 "
        "{%0,%1,%2,%3},{%4,%5,%6,%7},{%8,%9},{%0,%1,%2,%3};\n"
        : "+f"(c[0]), "+f"(c[1]), "+f"(c[2]), "+f"(c[3])
        : "r"(a[0]), "r"(a[1]), "r"(a[2]), "r"(a[3]), "r"(b0), "r"(b1));
}

#define CSCALE 0.18033688011112042f   /* (1/8) * log2(e) */

// ---------------- kernel 1: sign masks ---------------------------------------
__global__ void mask_kernel(const float* __restrict__ q, const float* __restrict__ k) {
    int warp = threadIdx.x >> 5, lane = threadIdx.x & 31;
    int row = blockIdx.x * 4 + warp;
    const float4* q4 = reinterpret_cast<const float4*>(q + (size_t)row * ND);
    const float4* k4 = reinterpret_cast<const float4*>(k + (size_t)row * ND);
    float sq = 0.f, sk = 0.f;
#pragma unroll
    for (int i = 0; i < 4; i++) {
        float4 a = q4[lane + 32 * i];
        sq += fabsf(a.x) + fabsf(a.y) + fabsf(a.z) + fabsf(a.w);
        float4 b = k4[lane + 32 * i];
        sk += fabsf(b.x) + fabsf(b.y) + fabsf(b.z) + fabsf(b.w);
    }
#pragma unroll
    for (int o = 16; o; o >>= 1) {
        sq += __shfl_xor_sync(0xffffffffu, sq, o);
        sk += __shfl_xor_sync(0xffffffffu, sk, o);
    }
    if (lane == 0) {
        g_qm[row] = sq > 0.f ? 1.f : 0.f;
        g_km[row] = sk > 0.f ? 1.f : 0.f;
    }
}

// ---------------- kernel 2: fused projection GEMMs  C = X @ W^T + b ----------
__global__ __launch_bounds__(512, 1) void proj_kernel(
    const float* __restrict__ queries, const float* __restrict__ keys,
    const float* __restrict__ Wq, const float* __restrict__ bq,
    const float* __restrict__ Wk, const float* __restrict__ bk,
    const float* __restrict__ Wv, const float* __restrict__ bv) {
    const int which = blockIdx.z;
    const float* X    = (which == 0) ? queries : keys;
    const float* Wt   = (which == 0) ? Wq : (which == 1) ? Wk : Wv;
    const float* bias = (which == 0) ? bq : (which == 1) ? bk : bv;
    float* out        = (which == 0) ? g_Q : (which == 1) ? g_K : g_V;

    __shared__ float sA[2][4096];
    __shared__ float sB[2][4096];

    const int tid = threadIdx.x, wid = tid >> 5, lane = tid & 31;
    const int g = lane >> 2, tg = lane & 3;
    const int wm2 = (wid >> 2) * 2;
    const int wn4 = (wid & 3) * 4;
    const int m0 = blockIdx.y * 128, n0 = blockIdx.x * 128;

    const int rr  = tid >> 3;
    const int c4  = tid & 7;
    const int k8s = c4 >> 1, khis = c4 & 1;

    float acc[2][4][4];
#pragma unroll
    for (int mi = 0; mi < 2; mi++)
#pragma unroll
        for (int ni = 0; ni < 4; ni++)
#pragma unroll
            for (int e = 0; e < 4; e++) acc[mi][ni][e] = 0.f;

    float4 va[2], vb[2];

    auto ldg = [&](int kb) {
#pragma unroll
        for (int j = 0; j < 2; j++) {
            int r = rr + 64 * j;
            va[j] = *reinterpret_cast<const float4*>(X  + (size_t)(m0 + r) * ND + kb + c4 * 4);
            vb[j] = *reinterpret_cast<const float4*>(Wt + (size_t)(n0 + r) * ND + kb + c4 * 4);
        }
    };
    auto sts = [&](int buf) {
#pragma unroll
        for (int j = 0; j < 2; j++) {
            int r = rr + 64 * j;
            {
                int mblk = r >> 4, gg = r & 7, hi = (r >> 3) & 1;
                float* p = &sA[buf][((mblk * 4 + k8s) * 8 + gg) * 16 + hi + 2 * khis];
                p[((0 ^ k8s) & 3) * 4] = tf32r(va[j].x);
                p[((1 ^ k8s) & 3) * 4] = tf32r(va[j].y);
                p[((2 ^ k8s) & 3) * 4] = tf32r(va[j].z);
                p[((3 ^ k8s) & 3) * 4] = tf32r(va[j].w);
            }
            {
                int nblk = r >> 3, gg = r & 7;
                float* p = &sB[buf][((nblk * 4 + k8s) * 8 + gg) * 8 + khis];
                p[((0 ^ k8s) & 3) * 2] = tf32r(vb[j].x);
                p[((1 ^ k8s) & 3) * 2] = tf32r(vb[j].y);
                p[((2 ^ k8s) & 3) * 2] = tf32r(vb[j].z);
                p[((3 ^ k8s) & 3) * 2] = tf32r(vb[j].w);
            }
        }
    };

    ldg(0);
    sts(0);
    __syncthreads();

    for (int kb = 0, it = 0; kb < ND; kb += 32, it++) {
        const int buf = it & 1;
        const bool more = (kb + 32) < ND;
        if (more) ldg(kb + 32);
#pragma unroll
        for (int ks = 0; ks < 4; ks++) {
            const int slot = (tg ^ ks) & 3;
            float4 af[2];
            af[0] = *reinterpret_cast<const float4*>(
                &sA[buf][(((wm2 + 0) * 4 + ks) * 8 + g) * 16 + slot * 4]);
            af[1] = *reinterpret_cast<const float4*>(
                &sA[buf][(((wm2 + 1) * 4 + ks) * 8 + g) * 16 + slot * 4]);
            float2 bf[4];
#pragma unroll
            for (int ni = 0; ni < 4; ni++)
                bf[ni] = *reinterpret_cast<const float2*>(
                    &sB[buf][(((wn4 + ni) * 4 + ks) * 8 + g) * 8 + slot * 2]);
#pragma unroll
            for (int mi = 0; mi < 2; mi++)
#pragma unroll
                for (int ni = 0; ni < 4; ni++)
                    mma8(acc[mi][ni], reinterpret_cast<const uint32_t*>(&af[mi]),
                         __float_as_uint(bf[ni].x), __float_as_uint(bf[ni].y));
        }
        if (more) sts(buf ^ 1);
        __syncthreads();
    }

    // epilogue: store tf32-pre-rounded (attn consumes these values verbatim)
#pragma unroll
    for (int mi = 0; mi < 2; mi++) {
#pragma unroll
        for (int ni = 0; ni < 4; ni++) {
            int row = m0 + (wm2 + mi) * 16 + g;
            int col = n0 + (wn4 + ni) * 8 + 2 * tg;
            float b0 = bias[col], b1 = bias[col + 1];
            *reinterpret_cast<float2*>(out + (size_t)row * ND + col) =
                make_float2(tf32r(acc[mi][ni][0] + b0), tf32r(acc[mi][ni][1] + b1));
            *reinterpret_cast<float2*>(out + (size_t)(row + 8) * ND + col) =
                make_float2(tf32r(acc[mi][ni][2] + b0), tf32r(acc[mi][ni][3] + b1));
        }
    }
}

// ---------------- kernel 3: attention (single pass, unnormalized weights) ----
#define SQ_OFF  0
#define SKF_OFF 8192
#define SVF_OFF 12288
#define SW_OFF  16384
#define SKM_OFF 25088
#define ATTN_FLOATS 25216
#define ATTN_SMEM (ATTN_FLOATS * (int)sizeof(float))
#define SWS 68

__device__ __forceinline__ void stage_K_half(float* dst, const float* src, int tid) {
#pragma unroll
    for (int jj = 0; jj < 4; jj++) {
        int idx = tid + 256 * jj;
        int r = idx >> 4, c4 = idx & 15;
        float4 v = *reinterpret_cast<const float4*>(src + (size_t)r * ND + c4 * 4);
        int nblk = r >> 3, gk = r & 7, k8 = c4 >> 1, khi = c4 & 1;
        float* p = &dst[((nblk * 8 + k8) * 8 + gk) * 8 + khi];
        p[((0 ^ k8) & 3) * 2] = v.x;
        p[((1 ^ k8) & 3) * 2] = v.y;
        p[((2 ^ k8) & 3) * 2] = v.z;
        p[((3 ^ k8) & 3) * 2] = v.w;
    }
}

__device__ __forceinline__ void stage_V_half(float* dst, const float* src, int tid) {
#pragma unroll
    for (int jj = 0; jj < 4; jj++) {
        int idx = tid + 256 * jj;
        int r = idx >> 4, c4 = idx & 15;
        float4 v = *reinterpret_cast<const float4*>(src + (size_t)r * ND + c4 * 4);
        int nblk = c4 >> 1, k8 = r >> 3, tg = r & 3, khi = (r >> 2) & 1;
        int slot = ((tg ^ k8) & 3) * 2 + khi;
        int gb = (c4 & 1) * 4;
        float* p = &dst[((nblk * 8 + k8) * 8 + gb) * 8 + slot];
        p[0 * 8] = v.x;
        p[1 * 8] = v.y;
        p[2 * 8] = v.z;
        p[3 * 8] = v.w;
    }
}

__device__ __forceinline__ void smma_half(const float* sQ, const float* kbuf,
                                          int wid, int g, int tg, float (&acc)[8][4]) {
#pragma unroll
    for (int ni = 0; ni < 8; ni++)
#pragma unroll
        for (int e = 0; e < 4; e++) acc[ni][e] = 0.f;
#pragma unroll
    for (int ks = 0; ks < 8; ks++) {
        const int slot = (tg ^ ks) & 3;
        float4 a = *reinterpret_cast<const float4*>(
            &sQ[((wid * 8 + ks) * 8 + g) * 16 + slot * 4]);
#pragma unroll
        for (int ni = 0; ni < 8; ni++) {
            float2 bv = *reinterpret_cast<const float2*>(
                &kbuf[((ni * 8 + ks) * 8 + g) * 8 + slot * 2]);
            mma8(acc[ni], reinterpret_cast<const uint32_t*>(&a),
                 __float_as_uint(bv.x), __float_as_uint(bv.y));
        }
    }
}

__device__ __forceinline__ void mask_half(float (&acc)[8][4], const float* sKMh,
                                          int col0, int causal, int rowg0, int rowg1, int tg) {
#pragma unroll
    for (int ni = 0; ni < 8; ni++)
#pragma unroll
        for (int e = 0; e < 4; e++) {
            int r = e >> 1, c = e & 1;
            int cl = ni * 8 + 2 * tg + c;
            float t = acc[ni][e] * CSCALE;
            if (sKMh[cl] == 0.f) t = -CUDART_INF_F;
            if (causal && (col0 + cl) > (r ? rowg1 : rowg0)) t = -CUDART_INF_F;
            acc[ni][e] = fminf(t, 80.f);
        }
}

__global__ __launch_bounds__(256, 2) void attn_kernel(
    const int* __restrict__ causality, float* __restrict__ outp, float* __restrict__ attnp) {
    extern __shared__ float sh[];
    float* sQ  = sh + SQ_OFF;
    float* sKf = sh + SKF_OFF;
    float* sVf = sh + SVF_OFF;
    float* sW  = sh + SW_OFF;
    float* sKM = sh + SKM_OFF;

    const int qt = blockIdx.x, h = blockIdx.y, b = blockIdx.z;
    const int tid = threadIdx.x, wid = tid >> 5, lane = tid & 31;
    const int g = lane >> 2, tg = lane & 3;
    const int causal = *causality;
    const int q0 = qt * 128;

    // ---- stage Q (already tf32-rounded by proj) ----
    {
        const float* qsrc = g_Q + ((size_t)(b * NL + q0) * ND + h * NDH);
#pragma unroll
        for (int jj = 0; jj < 8; jj++) {
            int idx = tid + 256 * jj;
            int r = idx >> 4, c4 = idx & 15;
            float4 v = *reinterpret_cast<const float4*>(qsrc + (size_t)r * ND + c4 * 4);
            int mblk = r >> 4, gg = r & 7, hi = (r >> 3) & 1, k8 = c4 >> 1, khi = c4 & 1;
            float* p = &sQ[((mblk * 8 + k8) * 8 + gg) * 16 + hi + 2 * khi];
            p[((0 ^ k8) & 3) * 4] = v.x;
            p[((1 ^ k8) & 3) * 4] = v.y;
            p[((2 ^ k8) & 3) * 4] = v.z;
            p[((3 ^ k8) & 3) * 4] = v.w;
        }
    }

    const int rowl0 = wid * 16 + g, rowl1 = rowl0 + 8;
    const int rowg0 = q0 + rowl0, rowg1 = q0 + rowl1;
    const float qm0 = g_qm[b * NL + rowg0];
    const float qm1 = g_qm[b * NL + rowg1];

    float lrun[2] = {0.f, 0.f};
    const int ktmax = causal ? qt : 3;
    float acc[8][4];

    float oacc[8][4];
#pragma unroll
    for (int ni = 0; ni < 8; ni++)
#pragma unroll
        for (int e = 0; e < 4; e++) oacc[ni][e] = 0.f;

    // ---- SINGLE PASS: E = exp2(masked logits), l += rowsum, O += E*V --------
    for (int kt = 0; kt <= ktmax; kt++) {
        const float* kbase = g_K + ((size_t)(b * NL + kt * 128) * ND + h * NDH);
        const float* vbase = g_V + ((size_t)(b * NL + kt * 128) * ND + h * NDH);

#pragma unroll
        for (int half = 0; half < 2; half++) {
            stage_K_half(sKf, kbase + (size_t)(half * 64) * ND, tid);
            stage_V_half(sVf, vbase + (size_t)(half * 64) * ND, tid);
            if (half == 0 && tid < 128) sKM[tid] = g_km[b * NL + kt * 128 + tid];
            __syncthreads();

            smma_half(sQ, sKf, wid, g, tg, acc);
            mask_half(acc, sKM + half * 64, kt * 128 + half * 64, causal, rowg0, rowg1, tg);

            float ps0 = 0.f, ps1 = 0.f;
#pragma unroll
            for (int ni = 0; ni < 8; ni++) {
                float w00 = ex2(acc[ni][0]);
                float w01 = ex2(acc[ni][1]);
                float w10 = ex2(acc[ni][2]);
                float w11 = ex2(acc[ni][3]);
                ps0 += w00 + w01;
                ps1 += w10 + w11;
                *reinterpret_cast<float2*>(&sW[rowl0 * SWS + ni * 8 + 2 * tg]) = make_float2(w00, w01);
                *reinterpret_cast<float2*>(&sW[rowl1 * SWS + ni * 8 + 2 * tg]) = make_float2(w10, w11);
            }
            ps0 += __shfl_xor_sync(0xffffffffu, ps0, 1);
            ps0 += __shfl_xor_sync(0xffffffffu, ps0, 2);
            ps1 += __shfl_xor_sync(0xffffffffu, ps1, 1);
            ps1 += __shfl_xor_sync(0xffffffffu, ps1, 2);
            lrun[0] += ps0;
            lrun[1] += ps1;
            __syncwarp();

            // unnormalized weights -> gmem (rescale kernel normalizes later)
            if (attnp) {
#pragma unroll
                for (int j = 0; j < 8; j++) {
                    int fidx = lane + 32 * j;
                    int rl = fidx >> 4, c4 = fidx & 15;
                    int row = wid * 16 + rl;
                    float4 v = *reinterpret_cast<const float4*>(&sW[row * SWS + c4 * 4]);
                    *reinterpret_cast<float4*>(
                        attnp + ((size_t)(b * NH + h) * NL + q0 + row) * NL +
                        kt * 128 + half * 64 + c4 * 4) = v;
                }
            }

            // O += E_half * V_half
            const float* wr0 = sW + (size_t)rowl0 * SWS;
            const float* wr1 = sW + (size_t)rowl1 * SWS;
#pragma unroll
            for (int ks = 0; ks < 8; ks++) {
                const int slot = (tg ^ ks) & 3;
                uint32_t a[4];
                a[0] = tf32u(wr0[ks * 8 + tg]);
                a[1] = tf32u(wr1[ks * 8 + tg]);
                a[2] = tf32u(wr0[ks * 8 + tg + 4]);
                a[3] = tf32u(wr1[ks * 8 + tg + 4]);
#pragma unroll
                for (int ni = 0; ni < 8; ni++) {
                    float2 bv = *reinterpret_cast<const float2*>(
                        &sVf[((ni * 8 + ks) * 8 + g) * 8 + slot * 2]);
                    mma8(oacc[ni], a, __float_as_uint(bv.x), __float_as_uint(bv.y));
                }
            }
            __syncthreads();
        }
    }

    float invl[2];
    invl[0] = lrun[0] > 0.f ? qm0 / lrun[0] : 0.f;
    invl[1] = lrun[1] > 0.f ? qm1 / lrun[1] : 0.f;

    if (tg == 0) {
        g_linv[(b * NH + h) * NL + rowg0] = invl[0];
        g_linv[(b * NH + h) * NL + rowg1] = invl[1];
    }

    // epilogue: out[b][q][h*64 + d] = O * (qm/l)
#pragma unroll
    for (int ni = 0; ni < 8; ni++) {
        int col = h * NDH + ni * 8 + 2 * tg;
        *reinterpret_cast<float2*>(outp + ((size_t)b * NL + rowg0) * ND + col) =
            make_float2(oacc[ni][0] * invl[0], oacc[ni][1] * invl[0]);
        *reinterpret_cast<float2*>(outp + ((size_t)b * NL + rowg1) * ND + col) =
            make_float2(oacc[ni][2] * invl[1], oacc[ni][3] * invl[1]);
    }
}

// ---------------- kernel 4: normalize weights + upper-triangle zero-fill -----
__global__ __launch_bounds__(256) void rescale_kernel(
    const int* __restrict__ causality, float* __restrict__ attnp) {
    const int causal = *causality;
    const int bh = blockIdx.x >> 6;
    const int rblk = blockIdx.x & 63;
    const int row = rblk * 8 + (threadIdx.x >> 5);
    const int lane = threadIdx.x & 31;
    const float linv = g_linv[bh * NL + row];
    float* base = attnp + ((size_t)bh * NL + row) * NL;
#pragma unroll
    for (int j = 0; j < 4; j++) {
        int col = j * 128 + lane * 4;
        float4* p = reinterpret_cast<float4*>(base + col);
        if (causal && col > row) {
            *p = make_float4(0.f, 0.f, 0.f, 0.f);
        } else {
            float4 v = *p;
            v.x = (causal && col     > row) ? 0.f : v.x * linv;
            v.y = (causal && col + 1 > row) ? 0.f : v.y * linv;
            v.z = (causal && col + 2 > row) ? 0.f : v.z * linv;
            v.w = (causal && col + 3 > row) ? 0.f : v.w * linv;
            *p = v;
        }
    }
}

// ---------------- launcher ----------------------------------------------------
extern "C" void kernel_launch(void* const* d_in, const int* in_sizes, int n_in,
                              void* d_out, int out_size) {
    (void)in_sizes; (void)n_in;
    const float* queries = (const float*)d_in[0];
    const float* keys    = (const float*)d_in[1];
    const float* Wq = (const float*)d_in[2];
    const float* bq = (const float*)d_in[3];
    const float* Wk = (const float*)d_in[4];
    const float* bk = (const float*)d_in[5];
    const float* Wv = (const float*)d_in[6];
    const float* bv = (const float*)d_in[7];
    const int* caus = (const int*)d_in[8];

    float* outp = (float*)d_out;
    const size_t o_elems = (size_t)NB * NL * ND;
    const size_t a_elems = (size_t)NB * NH * NL * NL;
    float* attnp = ((size_t)out_size >= o_elems + a_elems) ? (outp + o_elems) : nullptr;

    cudaFuncSetAttribute(attn_kernel, cudaFuncAttributeMaxDynamicSharedMemorySize, ATTN_SMEM);

    mask_kernel<<<MTOT / 4, 128>>>(queries, keys);
    proj_kernel<<<dim3(4, 128, 3), 512>>>(queries, keys, Wq, bq, Wk, bk, Wv, bv);
    attn_kernel<<<dim3(4, NH, NB), 256, ATTN_SMEM>>>(caus, outp, attnp);
    if (attnp) rescale_kernel<<<NB * NH * 64, 256>>>(caus, attnp);
}

// round 6
// speedup vs baseline: 1.5007x; 1.5007x over previous
#include <cuda_runtime.h>
#include <cuda_fp16.h>
#include <cstdint>

#define NB 32
#define NL 512
#define ND 512
#define NH 8
#define NDH 64
#define MTOT (NB*NL)

typedef unsigned int u32;

// ---------------- scratch (static device memory; no allocs allowed) ----------
__device__ uint4 g_Qh[(size_t)MTOT * ND / 8];   // fp16, row-major [MTOT][512]
__device__ uint4 g_Kh[(size_t)MTOT * ND / 8];
__device__ uint4 g_Vh[(size_t)MTOT * ND / 8];
__device__ float g_qm[MTOT];
__device__ float g_km[MTOT];

#define CSCALE 0.18033688011112042f   /* (1/8) * log2(e) */

// ---------------- helpers ----------------------------------------------------
__device__ __forceinline__ float ex2(float x) {
    float y;
    asm("ex2.approx.ftz.f32 %0, %1;" : "=f"(y) : "f"(x));
    return y;
}
// pack two f32 -> f16x2 u32, lo = first arg
__device__ __forceinline__ u32 pack2(float lo, float hi) {
    u32 r;
    asm("cvt.rn.f16x2.f32 %0, %1, %2;" : "=r"(r) : "f"(hi), "f"(lo));
    return r;
}
__device__ __forceinline__ void mma16(float c[4], const u32 a[4], u32 b0, u32 b1) {
    asm volatile(
        "mma.sync.aligned.m16n8k16.row.col.f32.f16.f16.f32 "
        "{%0,%1,%2,%3},{%4,%5,%6,%7},{%8,%9},{%0,%1,%2,%3};\n"
        : "+f"(c[0]), "+f"(c[1]), "+f"(c[2]), "+f"(c[3])
        : "r"(a[0]), "r"(a[1]), "r"(a[2]), "r"(a[3]), "r"(b0), "r"(b1));
}
__device__ __forceinline__ void ldsm4(u32 r[4], u32 a) {
    asm volatile("ldmatrix.sync.aligned.m8n8.x4.shared.b16 {%0,%1,%2,%3},[%4];"
                 : "=r"(r[0]), "=r"(r[1]), "=r"(r[2]), "=r"(r[3]) : "r"(a));
}
__device__ __forceinline__ void ldsm4t(u32 r[4], u32 a) {
    asm volatile("ldmatrix.sync.aligned.m8n8.x4.trans.shared.b16 {%0,%1,%2,%3},[%4];"
                 : "=r"(r[0]), "=r"(r[1]), "=r"(r[2]), "=r"(r[3]) : "r"(a));
}
__device__ __forceinline__ u32 sptr(const void* p) {
    return (u32)__cvta_generic_to_shared(p);
}

// ---------------- kernel 1: sign masks ---------------------------------------
__global__ void mask_kernel(const float* __restrict__ q, const float* __restrict__ k) {
    int warp = threadIdx.x >> 5, lane = threadIdx.x & 31;
    int row = blockIdx.x * 4 + warp;
    const float4* q4 = reinterpret_cast<const float4*>(q + (size_t)row * ND);
    const float4* k4 = reinterpret_cast<const float4*>(k + (size_t)row * ND);
    float sq = 0.f, sk = 0.f;
#pragma unroll
    for (int i = 0; i < 4; i++) {
        float4 a = q4[lane + 32 * i];
        sq += fabsf(a.x) + fabsf(a.y) + fabsf(a.z) + fabsf(a.w);
        float4 b = k4[lane + 32 * i];
        sk += fabsf(b.x) + fabsf(b.y) + fabsf(b.z) + fabsf(b.w);
    }
#pragma unroll
    for (int o = 16; o; o >>= 1) {
        sq += __shfl_xor_sync(0xffffffffu, sq, o);
        sk += __shfl_xor_sync(0xffffffffu, sk, o);
    }
    if (lane == 0) {
        g_qm[row] = sq > 0.f ? 1.f : 0.f;
        g_km[row] = sk > 0.f ? 1.f : 0.f;
    }
}

// ---------------- kernel 2: fused fp16 projection GEMMs ----------------------
// C = X @ W^T + b, inputs converted fp16, fp32 accum, fp16 output scratch.
// CTA tile 128x128, k-step 64, double-buffered row-major smem + XOR swizzle.
#define PROJ_SMEM (4 * 128 * 64 * 2)   // 2 bufs x (A+B) x 8192 halves x 2B = 64KB

__global__ __launch_bounds__(512, 1) void proj_kernel(
    const float* __restrict__ queries, const float* __restrict__ keys,
    const float* __restrict__ Wq, const float* __restrict__ bq,
    const float* __restrict__ Wk, const float* __restrict__ bk,
    const float* __restrict__ Wv, const float* __restrict__ bv) {
    extern __shared__ char smem_raw[];
    u32* sAu = reinterpret_cast<u32*>(smem_raw);          // [2][4096] u32 (A bufs)
    u32* sBu = sAu + 8192;                                 // [2][4096] u32 (B bufs)
    const u32 sA0 = sptr(sAu), sB0 = sptr(sBu);

    const int which = blockIdx.z;
    const float* X    = (which == 0) ? queries : keys;
    const float* Wt   = (which == 0) ? Wq : (which == 1) ? Wk : Wv;
    const float* bias = (which == 0) ? bq : (which == 1) ? bk : bv;
    u32* out = reinterpret_cast<u32*>((which == 0) ? g_Qh : (which == 1) ? g_Kh : g_Vh);

    const int tid = threadIdx.x, wid = tid >> 5, lane = tid & 31;
    const int g = lane >> 2, tg = lane & 3;
    const int wm = (wid >> 2) * 32, wn = (wid & 3) * 32;
    const int m0 = blockIdx.y * 128, n0 = blockIdx.x * 128;
    const int l7 = lane & 7, mat = lane >> 3;

    // staging tasks: 1024 chunk-tasks per matrix / 512 threads = 2 each
    int tr[2], tc[2];
#pragma unroll
    for (int j = 0; j < 2; j++) {
        int idx = tid + 512 * j;
        tr[j] = idx >> 3;
        tc[j] = idx & 7;
    }

    float acc[2][4][4];
#pragma unroll
    for (int mi = 0; mi < 2; mi++)
#pragma unroll
        for (int ni = 0; ni < 4; ni++)
#pragma unroll
            for (int e = 0; e < 4; e++) acc[mi][ni][e] = 0.f;

    float4 va[2][2], vb[2][2];
    auto ldg = [&](int kb) {
#pragma unroll
        for (int j = 0; j < 2; j++) {
            const float* ap = X + (size_t)(m0 + tr[j]) * ND + kb + tc[j] * 8;
            va[j][0] = *reinterpret_cast<const float4*>(ap);
            va[j][1] = *reinterpret_cast<const float4*>(ap + 4);
            const float* bp = Wt + (size_t)(n0 + tr[j]) * ND + kb + tc[j] * 8;
            vb[j][0] = *reinterpret_cast<const float4*>(bp);
            vb[j][1] = *reinterpret_cast<const float4*>(bp + 4);
        }
    };
    auto sts = [&](int buf) {
#pragma unroll
        for (int j = 0; j < 2; j++) {
            int off = tr[j] * 32 + ((tc[j] ^ (tr[j] & 7)) * 4);
            uint4 wa = make_uint4(pack2(va[j][0].x, va[j][0].y), pack2(va[j][0].z, va[j][0].w),
                                  pack2(va[j][1].x, va[j][1].y), pack2(va[j][1].z, va[j][1].w));
            *reinterpret_cast<uint4*>(sAu + buf * 4096 + off) = wa;
            uint4 wb = make_uint4(pack2(vb[j][0].x, vb[j][0].y), pack2(vb[j][0].z, vb[j][0].w),
                                  pack2(vb[j][1].x, vb[j][1].y), pack2(vb[j][1].z, vb[j][1].w));
            *reinterpret_cast<uint4*>(sBu + buf * 4096 + off) = wb;
        }
    };

    ldg(0);
    sts(0);
    __syncthreads();

    for (int kb = 0, it = 0; kb < ND; kb += 64, it++) {
        const int buf = it & 1;
        const bool more = (kb + 64) < ND;
        if (more) ldg(kb + 64);
#pragma unroll
        for (int ks = 0; ks < 4; ks++) {
            u32 af[2][4], bf[2][4];
#pragma unroll
            for (int mi = 0; mi < 2; mi++) {
                int row = wm + mi * 16 + (mat & 1) * 8 + l7;
                int chunk = 2 * ks + (mat >> 1);
                ldsm4(af[mi], sA0 + buf * 16384 + row * 128 + ((chunk ^ l7) << 4));
            }
#pragma unroll
            for (int np = 0; np < 2; np++) {
                int nb = (wn >> 3) + 2 * np + (mat >> 1);
                int row = nb * 8 + l7;
                int chunk = 2 * ks + (mat & 1);
                ldsm4(bf[np], sB0 + buf * 16384 + row * 128 + ((chunk ^ l7) << 4));
            }
#pragma unroll
            for (int mi = 0; mi < 2; mi++)
#pragma unroll
                for (int ni = 0; ni < 4; ni++)
                    mma16(acc[mi][ni], af[mi], bf[ni >> 1][(ni & 1) * 2], bf[ni >> 1][(ni & 1) * 2 + 1]);
        }
        if (more) sts(buf ^ 1);
        __syncthreads();
    }

    // epilogue: +bias, pack fp16, store
#pragma unroll
    for (int mi = 0; mi < 2; mi++) {
#pragma unroll
        for (int ni = 0; ni < 4; ni++) {
            int row = m0 + wm + mi * 16 + g;
            int col = n0 + wn + ni * 8 + 2 * tg;
            float2 bv2 = *reinterpret_cast<const float2*>(bias + col);
            out[((size_t)row * ND + col) >> 1] =
                pack2(acc[mi][ni][0] + bv2.x, acc[mi][ni][1] + bv2.y);
            out[((size_t)(row + 8) * ND + col) >> 1] =
                pack2(acc[mi][ni][2] + bv2.x, acc[mi][ni][3] + bv2.y);
        }
    }
}

// ---------------- kernel 3: fp16 flash attention + fused weight normalize ----
// smem: sQ 16KB + sK 16KB + sV 16KB + km/linv 1KB = 50176B -> occupancy 2
#define ATTN_SMEM (3 * 8192 * 2 + 256 * 4)

__global__ __launch_bounds__(256, 2) void attn_kernel(
    const int* __restrict__ causality, float* __restrict__ outp, float* __restrict__ attnp) {
    extern __shared__ char smem_raw[];
    u32* sQu = reinterpret_cast<u32*>(smem_raw);   // 4096 u32
    u32* sKu = sQu + 4096;
    u32* sVu = sKu + 4096;
    float* sKM  = reinterpret_cast<float*>(sVu + 4096);   // 128
    float* sLin = sKM + 128;                               // 128
    const u32 sQ0 = sptr(sQu), sK0 = sptr(sKu), sV0 = sptr(sVu);

    const int qt = blockIdx.x, h = blockIdx.y, b = blockIdx.z;
    const int tid = threadIdx.x, wid = tid >> 5, lane = tid & 31;
    const int g = lane >> 2, tg = lane & 3;
    const int l7 = lane & 7, mat = lane >> 3;
    const int causal = *causality;
    const int q0 = qt * 128;

    // ---- stage Q (fp16, row-major + chunk swizzle) ----
    {
        const uint4* qsrc = g_Qh + (((size_t)(b * NL + q0) * ND + h * NDH) >> 3);
#pragma unroll
        for (int j = 0; j < 4; j++) {
            int idx = tid + 256 * j;
            int r = idx >> 3, c = idx & 7;
            *reinterpret_cast<uint4*>(sQu + r * 32 + ((c ^ (r & 7)) * 4)) = qsrc[r * 64 + c];
        }
    }
    __syncthreads();

    // ---- hoisted Q A-fragments (persist across all kv tiles) ----
    u32 aq[4][4];
#pragma unroll
    for (int ks = 0; ks < 4; ks++) {
        int row = wid * 16 + (mat & 1) * 8 + l7;
        int chunk = 2 * ks + (mat >> 1);
        ldsm4(aq[ks], sQ0 + row * 128 + ((chunk ^ l7) << 4));
    }

    const int rowl0 = wid * 16 + g, rowl1 = rowl0 + 8;
    const int rowg0 = q0 + rowl0, rowg1 = q0 + rowl1;
    const float qm0 = g_qm[b * NL + rowg0];
    const float qm1 = g_qm[b * NL + rowg1];

    float lrun[2] = {0.f, 0.f};
    const int ktmax = causal ? qt : 3;

    float oacc[8][4];
#pragma unroll
    for (int ni = 0; ni < 8; ni++)
#pragma unroll
        for (int e = 0; e < 4; e++) oacc[ni][e] = 0.f;

    for (int kt = 0; kt <= ktmax; kt++) {
        __syncthreads();   // previous-iter readers done before restage
        {
            const uint4* kbase = g_Kh + (((size_t)(b * NL + kt * 128) * ND + h * NDH) >> 3);
            const uint4* vbase = g_Vh + (((size_t)(b * NL + kt * 128) * ND + h * NDH) >> 3);
#pragma unroll
            for (int j = 0; j < 4; j++) {
                int idx = tid + 256 * j;
                int r = idx >> 3, c = idx & 7;
                int off = r * 32 + ((c ^ (r & 7)) * 4);
                *reinterpret_cast<uint4*>(sKu + off) = kbase[r * 64 + c];
                *reinterpret_cast<uint4*>(sVu + off) = vbase[r * 64 + c];
            }
            if (tid < 128) sKM[tid] = g_km[b * NL + kt * 128 + tid];
        }
        __syncthreads();

#pragma unroll
        for (int hf = 0; hf < 2; hf++) {
            // ---- S = Q K^T over 64 kv cols ----
            float acc[8][4];
#pragma unroll
            for (int ni = 0; ni < 8; ni++)
#pragma unroll
                for (int e = 0; e < 4; e++) acc[ni][e] = 0.f;
#pragma unroll
            for (int np = 0; np < 4; np++) {
#pragma unroll
                for (int ks = 0; ks < 4; ks++) {
                    u32 kb4[4];
                    int nb = 2 * np + (mat >> 1);
                    int row = 64 * hf + nb * 8 + l7;
                    int chunk = 2 * ks + (mat & 1);
                    ldsm4(kb4, sK0 + row * 128 + ((chunk ^ l7) << 4));
                    mma16(acc[2 * np], aq[ks], kb4[0], kb4[1]);
                    mma16(acc[2 * np + 1], aq[ks], kb4[2], kb4[3]);
                }
            }

            // ---- mask, exp2, rowsum, direct weight store ----
            float ps0 = 0.f, ps1 = 0.f;
            float* wrow0 = attnp ? (attnp + ((size_t)(b * NH + h) * NL + rowg0) * NL + kt * 128 + hf * 64) : nullptr;
#pragma unroll
            for (int ni = 0; ni < 8; ni++) {
                int cl = ni * 8 + 2 * tg;
                int cg = kt * 128 + hf * 64 + cl;
                float km0 = sKM[hf * 64 + cl], km1 = sKM[hf * 64 + cl + 1];
                float m00 = (causal && (cg     > rowg0)) ? 0.f : km0;
                float m01 = (causal && (cg + 1 > rowg0)) ? 0.f : km1;
                float m10 = (causal && (cg     > rowg1)) ? 0.f : km0;
                float m11 = (causal && (cg + 1 > rowg1)) ? 0.f : km1;
                float e00 = ex2(fminf(acc[ni][0] * CSCALE, 15.f)) * m00;
                float e01 = ex2(fminf(acc[ni][1] * CSCALE, 15.f)) * m01;
                float e10 = ex2(fminf(acc[ni][2] * CSCALE, 15.f)) * m10;
                float e11 = ex2(fminf(acc[ni][3] * CSCALE, 15.f)) * m11;
                ps0 += e00 + e01;
                ps1 += e10 + e11;
                acc[ni][0] = e00; acc[ni][1] = e01; acc[ni][2] = e10; acc[ni][3] = e11;
                if (wrow0) {
                    *reinterpret_cast<float2*>(wrow0 + cl) = make_float2(e00, e01);
                    *reinterpret_cast<float2*>(wrow0 + 8 * NL + cl) = make_float2(e10, e11);
                }
            }
            ps0 += __shfl_xor_sync(0xffffffffu, ps0, 1);
            ps0 += __shfl_xor_sync(0xffffffffu, ps0, 2);
            ps1 += __shfl_xor_sync(0xffffffffu, ps1, 1);
            ps1 += __shfl_xor_sync(0xffffffffu, ps1, 2);
            lrun[0] += ps0;
            lrun[1] += ps1;

            // ---- pack E c-frag -> a-frag (registers only) ----
            u32 ef[4][4];
#pragma unroll
            for (int ks = 0; ks < 4; ks++) {
                ef[ks][0] = pack2(acc[2 * ks][0], acc[2 * ks][1]);
                ef[ks][1] = pack2(acc[2 * ks][2], acc[2 * ks][3]);
                ef[ks][2] = pack2(acc[2 * ks + 1][0], acc[2 * ks + 1][1]);
                ef[ks][3] = pack2(acc[2 * ks + 1][2], acc[2 * ks + 1][3]);
            }

            // ---- O += E V (ldmatrix.trans for V) ----
#pragma unroll
            for (int np = 0; np < 4; np++) {
#pragma unroll
                for (int ks = 0; ks < 4; ks++) {
                    u32 vb4[4];
                    int nb = 2 * np + (mat >> 1);
                    int row = 64 * hf + 16 * ks + (mat & 1) * 8 + l7;
                    ldsm4t(vb4, sV0 + row * 128 + ((nb ^ l7) << 4));
                    mma16(oacc[2 * np], ef[ks], vb4[0], vb4[1]);
                    mma16(oacc[2 * np + 1], ef[ks], vb4[2], vb4[3]);
                }
            }
        }
    }

    float invl[2];
    invl[0] = lrun[0] > 0.f ? qm0 / lrun[0] : 0.f;
    invl[1] = lrun[1] > 0.f ? qm1 / lrun[1] : 0.f;
    if (tg == 0) {
        sLin[rowl0] = invl[0];
        sLin[rowl1] = invl[1];
    }

    // ---- O epilogue ----
#pragma unroll
    for (int ni = 0; ni < 8; ni++) {
        int col = h * NDH + ni * 8 + 2 * tg;
        *reinterpret_cast<float2*>(outp + ((size_t)b * NL + rowg0) * ND + col) =
            make_float2(oacc[ni][0] * invl[0], oacc[ni][1] * invl[0]);
        *reinterpret_cast<float2*>(outp + ((size_t)b * NL + rowg1) * ND + col) =
            make_float2(oacc[ni][2] * invl[1], oacc[ni][3] * invl[1]);
    }

    // ---- fused weight normalization (L2-hot read-back of own rows) ----
    if (attnp) {
        __syncthreads();   // sLin visible + all weight STGs ordered (block scope)
        float* wbase = attnp + ((size_t)(b * NH + h) * NL + q0) * NL;
        const int lim = causal ? (qt + 1) * 128 : NL;
        const float4 z4 = make_float4(0.f, 0.f, 0.f, 0.f);
#pragma unroll 4
        for (int j = 0; j < 64; j++) {
            int idx = tid + 256 * j;
            int row = idx >> 7, c4 = idx & 127;
            int col = c4 * 4;
            float4* p = reinterpret_cast<float4*>(wbase + (size_t)row * NL + col);
            if (col >= lim) {
                *p = z4;               // never-written causal tiles: zero-fill only
            } else {
                float li = sLin[row];
                float4 v = *p;
                v.x *= li; v.y *= li; v.z *= li; v.w *= li;
                *p = v;
            }
        }
    }
}

// ---------------- launcher ----------------------------------------------------
extern "C" void kernel_launch(void* const* d_in, const int* in_sizes, int n_in,
                              void* d_out, int out_size) {
    (void)in_sizes; (void)n_in;
    const float* queries = (const float*)d_in[0];
    const float* keys    = (const float*)d_in[1];
    const float* Wq = (const float*)d_in[2];
    const float* bq = (const float*)d_in[3];
    const float* Wk = (const float*)d_in[4];
    const float* bk = (const float*)d_in[5];
    const float* Wv = (const float*)d_in[6];
    const float* bv = (const float*)d_in[7];
    const int* caus = (const int*)d_in[8];

    float* outp = (float*)d_out;
    const size_t o_elems = (size_t)NB * NL * ND;
    const size_t a_elems = (size_t)NB * NH * NL * NL;
    float* attnp = ((size_t)out_size >= o_elems + a_elems) ? (outp + o_elems) : nullptr;

    cudaFuncSetAttribute(proj_kernel, cudaFuncAttributeMaxDynamicSharedMemorySize, PROJ_SMEM);
    cudaFuncSetAttribute(attn_kernel, cudaFuncAttributeMaxDynamicSharedMemorySize, ATTN_SMEM);

    mask_kernel<<<MTOT / 4, 128>>>(queries, keys);
    proj_kernel<<<dim3(4, 128, 3), 512, PROJ_SMEM>>>(queries, keys, Wq, bq, Wk, bk, Wv, bv);
    attn_kernel<<<dim3(4, NH, NB), 256, ATTN_SMEM>>>(caus, outp, attnp);
}